// round 17
// baseline (speedup 1.0000x reference)
#include <cuda_runtime.h>
#include <cuda_fp16.h>
#include <cmath>
#include <cstdint>

typedef unsigned int u32;
typedef unsigned long long u64;

#define NPTS   131072
#define TMASK  524287u
#define NLVL   24
#define ODIM   896
#define HTILES 512          // 128-row tiles per half

__device__ __align__(128) __half g_X[25165824];   // 131072 x 192
__device__ __align__(128) __half g_W[524288];

// [cin 256x192][din 256x192][h0 256x256][h1][h2][cout 512x256][dout 384x256]
#define W_IN   0
#define W_H    98304
#define W_COUT 294912
#define W_DOUT 425984

struct ResArr { float r[NLVL]; };

__device__ __forceinline__ u32 swz(u32 b) { return b ^ ((b >> 3) & 0x70); }

__device__ __forceinline__ u32 smem_u32(const void* p) {
    u32 a;
    asm("{ .reg .u64 t; cvta.to.shared.u64 t, %1; cvt.u32.u64 %0, t; }"
        : "=r"(a) : "l"(p));
    return a;
}

__device__ __forceinline__ void cpa16(u32 dst, const void* src) {
    asm volatile("cp.async.cg.shared.global [%0], [%1], 16;" :: "r"(dst), "l"(src));
}

#define LDSM4(R, ADDR) \
    asm volatile("ldmatrix.sync.aligned.m8n8.x4.shared.b16 {%0,%1,%2,%3}, [%4];" \
        : "=r"((R)[0]), "=r"((R)[1]), "=r"((R)[2]), "=r"((R)[3]) : "r"(ADDR))

#define MMA16816(D, A, B) \
    asm volatile("mma.sync.aligned.m16n8k16.row.col.f32.f16.f16.f32 " \
        "{%0,%1,%2,%3},{%4,%5,%6,%7},{%8,%9},{%0,%1,%2,%3};" \
        : "+f"((D)[0]), "+f"((D)[1]), "+f"((D)[2]), "+f"((D)[3]) \
        : "r"((A)[0]), "r"((A)[1]), "r"((A)[2]), "r"((A)[3]), \
          "r"((B)[0]), "r"((B)[1]))

__device__ __forceinline__ u32 pack2h(float a, float b) {
    __half2 h = __floats2half2_rn(a, b);
    return *(u32*)&h;
}

// ---------------------------------------------------------------------------
__global__ __launch_bounds__(256) void convert_all_w(
    const float* cin, const float* ch, const float* cout,
    const float* din, const float* dout,
    __half* __restrict__ w)
{
    const float* srcs[7] = {cin, din, ch, ch + 65536, ch + 131072, cout, dout};
    const int   Ks[7]    = {192, 192, 256, 256, 256, 256, 256};
    const int   Ns[7]    = {256, 256, 256, 256, 256, 512, 384};

    for (int id = blockIdx.x * 256 + threadIdx.x; id < 524288; id += gridDim.x * 256) {
        int base = 0, j = -1, rel = 0;
        #pragma unroll
        for (int t = 0; t < 7; t++) {
            int sz = Ks[t] * Ns[t];
            if (j < 0 && id < base + sz) { j = t; rel = id - base; }
            base += sz;
        }
        int K = Ks[j], N = Ns[j];
        int n = rel / K, k = rel % K;
        w[id] = __float2half(srcs[j][(size_t)k * N + n]);
    }
}

// ---------------------------------------------------------------------------
__global__ __launch_bounds__(256) void encode_kernel(
    const float* __restrict__ pos,
    const float* __restrict__ table0,
    const float* __restrict__ table1,
    __half* __restrict__ xout, ResArr rp, int tbase)
{
    extern __shared__ char sm[];
    int tid  = threadIdx.x;
    int warp = tid >> 5, lane = tid & 31;
    int pp = lane >> 1, h = lane & 1;
    int row = warp * 16 + pp;
    int bx = blockIdx.x + tbase;
    int i = bx * 128 + row;

    float px = pos[3 * i + 0];
    float py = pos[3 * i + 1];
    float pz = pos[3 * i + 2];
    float mag = sqrtf(px * px + py * py + pz * pz);
    if (mag >= 1.0f) {
        float inv = 1.0f / mag;
        float s = (2.0f - inv) * inv;
        px *= s; py *= s; pz *= s;
    }
    px = (px + 2.0f) * 0.25f;
    py = (py + 2.0f) * 0.25f;
    pz = (pz + 2.0f) * 0.25f;

    #pragma unroll 1
    for (int l = 0; l < NLVL; l++) {
        const float* tab = (l < 12)
            ? (table0 + (size_t)l        * ((size_t)524288 * 8))
            : (table1 + (size_t)(l - 12) * ((size_t)524288 * 8));
        float res = rp.r[l];
        float x = px * res, y = py * res, z = pz * res;
        float fx = floorf(x), fy = floorf(y), fz = floorf(z);
        float wx = x - fx, wy = y - fy, wz = z - fz;
        unsigned x0 = (unsigned)fx, y0 = (unsigned)fy, z0 = (unsigned)fz;

        float f0 = 0.f, f1 = 0.f, f2 = 0.f, f3 = 0.f;
        #pragma unroll
        for (int c = 0; c < 8; c++) {
            unsigned cx = x0 + ((c >> 2) & 1);
            unsigned cy = y0 + ((c >> 1) & 1);
            unsigned cz = z0 + (c & 1);
            unsigned hh = cx ^ (cy * 2654435761u) ^ (cz * 805459861u);
            unsigned idx = hh & TMASK;
            float w = ((c & 4) ? wx : 1.0f - wx)
                    * ((c & 2) ? wy : 1.0f - wy)
                    * ((c & 1) ? wz : 1.0f - wz);
            float4 v = __ldg((const float4*)(tab + (size_t)idx * 8) + h);
            f0 += w * v.x; f1 += w * v.y; f2 += w * v.z; f3 += w * v.w;
        }
        u32 off = (u32)row * 384 + (u32)l * 16 + (u32)h * 8;
        *(u32*)(sm + off)     = pack2h(f0, f1);
        *(u32*)(sm + off + 4) = pack2h(f2, f3);
    }
    __syncthreads();

    const float4* sh = (const float4*)sm;
    float4* dh = (float4*)(xout + (size_t)bx * 128 * 192);
    #pragma unroll
    for (int j = 0; j < 12; j++)
        dh[tid + j * 256] = sh[tid + j * 256];
}

// ---------------------------------------------------------------------------
// Fused MLP: one CTA = 128 rows through all 9 GEMM passes.
// smem: PING 64KB @0, PONG 64KB @65536, WBUF 2x32KB @131072. 512 thr, 1 CTA/SM.
// ---------------------------------------------------------------------------
__global__ __launch_bounds__(512, 1) void fused_mlp(
    const __half* __restrict__ X, const __half* __restrict__ W,
    float* __restrict__ out, int ybase)
{
    extern __shared__ char sm[];
    u32 smb = smem_u32(sm);
    const u32 PING = 0, PONG = 65536, WB = 131072;
    int tid = threadIdx.x, lane = tid & 31, warp = tid >> 5;
    int wr = warp & 3, wc = warp >> 2;
    int by = blockIdx.x + ybase;

    // load X tile (3 chunks) into PING
    {
        const char* xP = (const char*)X + (size_t)by * 128 * 384;
        #pragma unroll
        for (int i = 0; i < 6; i++) {
            u32 q = tid + i * 512;
            u32 ch = q >> 10, u = q & 1023;
            u32 row = u >> 3, c16 = (u & 7) * 16;
            cpa16(smb + PING + ch * 16384 + swz(row * 128 + c16),
                  xP + row * 384 + ch * 128 + c16);
        }
        asm volatile("cp.async.commit_group;");
        asm volatile("cp.async.wait_group 0;");
        __syncthreads();
    }

    const int wOff[9]  = {W_IN, W_IN + 49152, W_DOUT, W_DOUT + 65536,
                          W_H, W_H + 65536, W_H + 131072, W_COUT, W_COUT + 65536};
    const int kcnA[9]  = {3, 3, 4, 4, 4, 4, 4, 4, 4};
    const int nValA[9] = {256, 256, 256, 128, 256, 256, 256, 256, 256};
    const u32 inBA[9]  = {PING, PING, PING, PING, PONG, PING, PONG, PING, PING};
    const int outBA[9] = {(int)PONG, (int)PING, -1, -1, (int)PING, (int)PONG, (int)PING, -1, -1};
    const int colbA[9] = {0, 0, 512, 768, 0, 0, 0, 0, 256};

    u32 aRowB = (u32)(wr * 32 + (lane & 15)) * 128;
    u32 aColB = (u32)((lane >> 4) << 4);
    u32 bRowL = (u32)(wc * 64 + ((lane >> 4) << 3) + (lane & 7));
    u32 bColB = (u32)(((lane >> 3) & 1) << 4);
    u32 bTile = (bRowL >> 7) * 16384;      // which 16KB subtile of the 32KB W chunk
    u32 bRowB = (bRowL & 127) * 128;       // row byte offset within subtile

    #pragma unroll 1
    for (int p = 0; p < 9; p++) {
        const char* Wp = (const char*)(W + wOff[p]);
        int kcn = kcnA[p], nV = nValA[p];
        u32 rowK2 = (u32)(kcn << 7);
        u32 inBase = inBA[p];
        int iters = nV >> 6;

        auto load_w = [&](int c, int buf) {
            u32 srcb = (u32)c * 128;
            for (int i = 0; i < iters; i++) {
                u32 q = tid + i * 512;
                u32 row = q >> 3, c16 = (q & 7) * 16;
                cpa16(smb + WB + (u32)buf * 32768 + (row >> 7) * 16384
                          + swz((row & 127) * 128 + c16),
                      Wp + row * rowK2 + srcb + c16);
            }
            asm volatile("cp.async.commit_group;");
        };

        float acc[2][8][4];
        #pragma unroll
        for (int m = 0; m < 2; m++)
            #pragma unroll
            for (int n = 0; n < 8; n++)
                #pragma unroll
                for (int j = 0; j < 4; j++) acc[m][n][j] = 0.f;

        load_w(0, 0);
        for (int c = 0; c < kcn; c++) {
            asm volatile("cp.async.wait_group 0;");
            __syncthreads();
            if (c + 1 < kcn) load_w(c + 1, (c + 1) & 1);

            u32 aB = smb + inBase + (u32)c * 16384;
            u32 bB = smb + WB + (u32)(c & 1) * 32768 + bTile;
            #pragma unroll
            for (int ks = 0; ks < 4; ks++) {
                u32 ah[2][4];
                #pragma unroll
                for (int m = 0; m < 2; m++)
                    LDSM4(ah[m], aB + swz(aRowB + (u32)m * 2048 + (u32)ks * 32 + aColB));
                u32 bh[4][4];
                #pragma unroll
                for (int nb = 0; nb < 4; nb++)
                    LDSM4(bh[nb], bB + swz(bRowB + (u32)nb * 2048 + (u32)ks * 32 + bColB));
                #pragma unroll
                for (int n8 = 0; n8 < 8; n8++) {
                    u32* fh = &bh[n8 >> 1][(n8 & 1) * 2];
                    MMA16816(acc[0][n8], ah[0], fh);
                    MMA16816(acc[1][n8], ah[1], fh);
                }
            }
        }
        __syncthreads();

        int rloc = wr * 32 + (lane >> 2);
        int cloc = (lane & 3) * 2;
        if (outBA[p] >= 0) {
            #pragma unroll
            for (int m = 0; m < 2; m++)
                #pragma unroll
                for (int n8 = 0; n8 < 8; n8++) {
                    u32 cc = (u32)(cloc + n8 * 8);
                    #pragma unroll
                    for (int h = 0; h < 2; h++) {
                        u32 row = (u32)(rloc + m * 16 + h * 8);
                        float a = fmaxf(acc[m][n8][2 * h], 0.f);
                        float b = fmaxf(acc[m][n8][2 * h + 1], 0.f);
                        *(u32*)(sm + (u32)outBA[p] + (u32)wc * 16384
                                + swz(row * 128 + cc * 2)) = pack2h(a, b);
                    }
                }
        } else if (wc * 64 < nV) {
            int cbase = colbA[p] + wc * 64 + cloc;
            #pragma unroll
            for (int m = 0; m < 2; m++)
                #pragma unroll
                for (int n8 = 0; n8 < 8; n8++) {
                    int col = cbase + n8 * 8;
                    #pragma unroll
                    for (int h = 0; h < 2; h++) {
                        size_t row = (size_t)(by * 128 + rloc + m * 16 + h * 8);
                        float2 v = make_float2(acc[m][n8][2 * h], acc[m][n8][2 * h + 1]);
                        *(float2*)(out + row * ODIM + col) = v;
                    }
                }
        }
        __syncthreads();
    }
}

// ---------------------------------------------------------------------------
__global__ __launch_bounds__(128) void normalize_clip(float* __restrict__ out, int rbase)
{
    float* p = out + (size_t)(blockIdx.x + rbase) * ODIM;
    int t = threadIdx.x;
    float v0 = p[t]       + 1e-8f;
    float v1 = p[t + 128] + 1e-8f;
    float v2 = p[t + 256] + 1e-8f;
    float v3 = p[t + 384] + 1e-8f;
    float ss = v0 * v0 + v1 * v1 + v2 * v2 + v3 * v3;
    #pragma unroll
    for (int o = 16; o > 0; o >>= 1)
        ss += __shfl_xor_sync(0xffffffffu, ss, o);
    __shared__ float ws[4];
    if ((t & 31) == 0) ws[t >> 5] = ss;
    __syncthreads();
    float tot = ws[0] + ws[1] + ws[2] + ws[3];
    float denom = fmaxf(sqrtf(tot), 1e-4f);
    p[t]       = v0 / denom;
    p[t + 128] = v1 / denom;
    p[t + 256] = v2 / denom;
    p[t + 384] = v3 / denom;
}

// ---------------------------------------------------------------------------
static void compute_resolutions(ResArr* rp)
{
    const double starts[2] = {16.0, 128.0};
    const double ends[2]   = {128.0, 512.0};
    for (int h = 0; h < 2; h++) {
        double growth = exp((log(ends[h]) - log(starts[h])) / 11.0);
        for (int k = 0; k < 12; k++)
            rp->r[h * 12 + k] = (float)floor(starts[h] * pow(growth, (double)k));
    }
}

extern "C" void kernel_launch(void* const* d_in, const int* in_sizes, int n_in,
                              void* d_out, int out_size)
{
    const float* positions  = (const float*)d_in[0];
    const float* table0     = (const float*)d_in[1];
    const float* table1     = (const float*)d_in[2];
    const float* clip_w_in  = (const float*)d_in[3];
    const float* clip_w_h   = (const float*)d_in[4];
    const float* clip_w_out = (const float*)d_in[5];
    const float* dino_w_in  = (const float*)d_in[6];
    const float* dino_w_out = (const float*)d_in[7];
    float* out = (float*)d_out;

    __half *X, *W;
    cudaGetSymbolAddress((void**)&X, g_X);
    cudaGetSymbolAddress((void**)&W, g_W);

    cudaFuncSetAttribute(encode_kernel, cudaFuncAttributeMaxDynamicSharedMemorySize, 49152);
    cudaFuncSetAttribute(fused_mlp, cudaFuncAttributeMaxDynamicSharedMemorySize, 196608);

    ResArr rp;
    compute_resolutions(&rp);

    static cudaStream_t sB = nullptr;
    static cudaEvent_t evF = nullptr, evW = nullptr, evE0 = nullptr, evB = nullptr;
    if (!sB) {
        cudaStreamCreateWithFlags(&sB, cudaStreamNonBlocking);
        cudaEventCreateWithFlags(&evF,  cudaEventDisableTiming);
        cudaEventCreateWithFlags(&evW,  cudaEventDisableTiming);
        cudaEventCreateWithFlags(&evE0, cudaEventDisableTiming);
        cudaEventCreateWithFlags(&evB,  cudaEventDisableTiming);
    }

    // FORK side stream from the capturing stream
    cudaEventRecord(evF, 0);
    cudaStreamWaitEvent(sB, evF, 0);

    convert_all_w<<<512, 256, 0, sB>>>(clip_w_in, clip_w_h, clip_w_out,
                                       dino_w_in, dino_w_out, W);
    cudaEventRecord(evW, sB);

    encode_kernel<<<HTILES, 256, 49152>>>(positions, table0, table1, X, rp, 0);
    cudaEventRecord(evE0, 0);

    cudaStreamWaitEvent(sB, evE0, 0);
    encode_kernel<<<HTILES, 256, 49152, sB>>>(positions, table0, table1, X, rp, HTILES);

    // half 0 on stream 0
    cudaStreamWaitEvent(0, evW, 0);
    fused_mlp<<<HTILES, 512, 196608>>>(X, W, out, 0);
    normalize_clip<<<NPTS / 2, 128>>>(out, 0);

    // half 1 on sB
    fused_mlp<<<HTILES, 512, 196608, sB>>>(X, W, out, HTILES);
    normalize_clip<<<NPTS / 2, 128, 0, sB>>>(out, NPTS / 2);
    cudaEventRecord(evB, sB);

    cudaStreamWaitEvent(0, evB, 0);
}